// round 3
// baseline (speedup 1.0000x reference)
#include <cuda_runtime.h>
#include <cuda_bf16.h>

// Closed-form theta-step: the 10-iteration relu fixed point solves exactly
// per sign of x.  x<=0: out=x, r=0.  x>0: out = x*1.5*(2-2^-11),
// r^2 = x^2*(1.5*2^-11)^2.  Single pass, fused scalar reduction.

#define NBLOCKS   3552      // 148 SMs * 24 blocks (3 waves at occ 8)
#define NTHREADS  256
#define NWARPS    (NTHREADS / 32)

__device__ float        g_partials[NBLOCKS];
__device__ unsigned int g_ticket = 0;

#define C_OUT  (1.5f * (2.0f - 0x1p-11f))            // 2.99853515625
#define C_R2   ((1.5f * 0x1p-11f) * (1.5f * 0x1p-11f))  // (e*2^-11)^2 / x^2

__global__ void __launch_bounds__(NTHREADS)
step_kernel(const float4* __restrict__ x4, float4* __restrict__ out4,
            int n4, float* __restrict__ out_scalar) {
    int tid    = blockIdx.x * NTHREADS + threadIdx.x;
    int stride = gridDim.x * NTHREADS;

    float local = 0.0f;
    for (int i = tid; i < n4; i += stride) {
        float4 v = __ldg(&x4[i]);
        float4 o;
        {
            float p = fmaxf(v.x, 0.0f), m = fminf(v.x, 0.0f);
            o.x = fmaf(C_OUT, p, m);  local = fmaf(p * p, C_R2, local);
        }
        {
            float p = fmaxf(v.y, 0.0f), m = fminf(v.y, 0.0f);
            o.y = fmaf(C_OUT, p, m);  local = fmaf(p * p, C_R2, local);
        }
        {
            float p = fmaxf(v.z, 0.0f), m = fminf(v.z, 0.0f);
            o.z = fmaf(C_OUT, p, m);  local = fmaf(p * p, C_R2, local);
        }
        {
            float p = fmaxf(v.w, 0.0f), m = fminf(v.w, 0.0f);
            o.w = fmaf(C_OUT, p, m);  local = fmaf(p * p, C_R2, local);
        }
        out4[i] = o;
    }

    // ---- block reduction of r^2 partial (fp32) ----
    #pragma unroll
    for (int off = 16; off > 0; off >>= 1)
        local += __shfl_down_sync(0xffffffffu, local, off);

    __shared__ float warpsum[NWARPS];
    int lane = threadIdx.x & 31;
    int wid  = threadIdx.x >> 5;
    if (lane == 0) warpsum[wid] = local;
    __syncthreads();

    __shared__ bool s_is_last;
    if (threadIdx.x == 0) {
        float v = 0.0f;
        #pragma unroll
        for (int w = 0; w < NWARPS; ++w) v += warpsum[w];
        g_partials[blockIdx.x] = v;
        __threadfence();
        unsigned int t = atomicAdd(&g_ticket, 1u);
        s_is_last = (t == (unsigned int)(gridDim.x - 1));
        if (s_is_last) g_ticket = 0;          // reset for graph replay
    }
    __syncthreads();

    // ---- last block: final reduction over all partials (double) ----
    if (s_is_last) {
        double acc = 0.0;
        for (int i = threadIdx.x; i < NBLOCKS; i += NTHREADS)
            acc += (double)g_partials[i];

        #pragma unroll
        for (int off = 16; off > 0; off >>= 1)
            acc += __shfl_down_sync(0xffffffffu, acc, off);

        __shared__ double dsum[NWARPS];
        if (lane == 0) dsum[wid] = acc;
        __syncthreads();

        if (threadIdx.x == 0) {
            double v = 0.0;
            #pragma unroll
            for (int w = 0; w < NWARPS; ++w) v += dsum[w];
            out_scalar[0] = (float)(0.5 * v);
        }
    }
}

extern "C" void kernel_launch(void* const* d_in, const int* in_sizes, int n_in,
                              void* d_out, int out_size) {
    const float* x = (const float*)d_in[0];
    float* out     = (float*)d_out;
    int n  = in_sizes[0];          // 67108864, divisible by 4
    int n4 = n >> 2;

    step_kernel<<<NBLOCKS, NTHREADS>>>((const float4*)x, (float4*)out, n4, out + n);
}